// round 17
// baseline (speedup 1.0000x reference)
#include <cuda_runtime.h>
#include <cuda_bf16.h>
#include <cstdint>

// Problem dims
#define BB   128
#define TT   256
#define HH   512
#define GG   2048
#define INN  1662
#define KP0  1664     // INN padded to 16B-aligned bf16 rows, multiple of 32
#define HD2  1024
#define NC   100
#define BT   32768

// ---------------- device scratch ----------------
__device__ float g_xpf[BT * GG];
__device__ float g_xpb[BT * GG];
__device__ float g_outbuf[BT * HD2];      // lstm_out fp32 (context path)
__device__ float g_hping[4 * BB * HH];
__device__ float g_scoresb[BT];
__device__ float g_attwb[BT];
__device__ float g_ctx[BB * HD2];
__device__ float g_hc[BB * HH];
// bf16 hi/lo planes
__device__ uint16_t g_xh[BT * KP0],  g_xl[BT * KP0];
__device__ uint16_t g_w0fh[GG * KP0], g_w0fl[GG * KP0];
__device__ uint16_t g_w0bh[GG * KP0], g_w0bl[GG * KP0];
__device__ uint16_t g_w1fh[GG * HD2], g_w1fl[GG * HD2];
__device__ uint16_t g_w1bh[GG * HD2], g_w1bl[GG * HD2];
__device__ uint16_t g_h0h[BT * HD2], g_h0l[BT * HD2];
__device__ uint16_t g_loh[BT * HD2], g_lol[BT * HD2];
__device__ uint16_t g_awth[HD2 * HD2], g_awtl[HD2 * HD2];

__device__ unsigned g_bcnt2[2] = {0, 0};
__device__ unsigned g_bgen2[2] = {0, 0};

__device__ __forceinline__ void mma_bf16(float* d, const uint32_t* a, const uint32_t* b) {
    asm volatile(
        "mma.sync.aligned.m16n8k16.row.col.f32.bf16.bf16.f32 "
        "{%0,%1,%2,%3}, {%4,%5,%6,%7}, {%8,%9}, {%0,%1,%2,%3};"
        : "+f"(d[0]), "+f"(d[1]), "+f"(d[2]), "+f"(d[3])
        : "r"(a[0]), "r"(a[1]), "r"(a[2]), "r"(a[3]), "r"(b[0]), "r"(b[1]));
}

__device__ __forceinline__ uint32_t smem_u32(const void* p) {
    uint32_t a;
    asm("{ .reg .u64 t; cvta.to.shared.u64 t, %1; cvt.u32.u64 %0, t; }" : "=r"(a) : "l"(p));
    return a;
}
__device__ __forceinline__ void cp_async16(uint32_t dst, const void* src) {
    asm volatile("cp.async.cg.shared.global [%0], [%1], 16;"
                 :: "r"(dst), "l"(src) : "memory");
}
__device__ __forceinline__ void cp_commit() {
    asm volatile("cp.async.commit_group;" ::: "memory");
}
__device__ __forceinline__ void cp_wait0() {
    asm volatile("cp.async.wait_group 0;" ::: "memory");
}

// split a float2 (k, k+1) into packed bf16x2 hi and residual-lo registers
__device__ __forceinline__ void split_bf16x2(float2 p, uint32_t& hi, uint32_t& lo) {
    __nv_bfloat162 h2 = __floats2bfloat162_rn(p.x, p.y);
    uint32_t hu; memcpy(&hu, &h2, 4);
    float f0 = __uint_as_float(hu << 16);
    float f1 = __uint_as_float(hu & 0xFFFF0000u);
    __nv_bfloat162 l2 = __floats2bfloat162_rn(p.x - f0, p.y - f1);
    uint32_t lu; memcpy(&lu, &l2, 4);
    hi = hu; lo = lu;
}

// ---------------- split (+pad) pass: fp32 [R][K] -> bf16 hi/lo planes [R][KP] ----------------
__global__ void split_pad_k(const float* __restrict__ src, uint16_t* __restrict__ dh,
                            uint16_t* __restrict__ dl, int R, int K, int KP)
{
    int n2 = R * (KP >> 1);
    int stride = gridDim.x * blockDim.x;
    int half = KP >> 1;
    for (int i = blockIdx.x * blockDim.x + threadIdx.x; i < n2; i += stride) {
        int r = i / half;
        int c = (i - r * half) * 2;
        float2 v = make_float2(0.f, 0.f);
        if (c + 1 < K)      v = *(const float2*)(src + (size_t)r * K + c);
        else if (c < K)     v.x = src[(size_t)r * K + c];
        uint32_t hi, lo;
        split_bf16x2(v, hi, lo);
        *(uint32_t*)(dh + (size_t)r * KP + c) = hi;
        *(uint32_t*)(dl + (size_t)r * KP + c) = lo;
    }
}

// ---------------- transpose + split: aw1 [K][N] -> planes [N][K] ----------------
__global__ void transpose_split_k(const float* __restrict__ src, uint16_t* __restrict__ dh,
                                  uint16_t* __restrict__ dl, int R, int Cc)
{
    __shared__ float t[32][33];
    int r0 = blockIdx.y * 32, c0 = blockIdx.x * 32;
    t[threadIdx.y][threadIdx.x] = src[(size_t)(r0 + threadIdx.y) * Cc + c0 + threadIdx.x];
    __syncthreads();
    if (threadIdx.x < 16) {
        float2 v = make_float2(t[2 * threadIdx.x][threadIdx.y],
                               t[2 * threadIdx.x + 1][threadIdx.y]);
        uint32_t hi, lo;
        split_bf16x2(v, hi, lo);
        size_t idx = (size_t)(c0 + threadIdx.y) * R + r0 + 2 * threadIdx.x;
        *(uint32_t*)(dh + idx) = hi;
        *(uint32_t*)(dl + idx) = lo;
    }
}

// ---------------- bf16-split GEMM (dual fwd+bwd): chunk32, 2-stage cp.async ----------------
// Operands pre-split into bf16 hi/lo planes (K multiple of 32, rows 16B-aligned).
// C = act(A*W^T + bias) with 3-term split: hi*hi + lo*hi + hi*lo, fp32 accum.
// Block 128x128, 8 warps 2(m)x4(n), 2 CTA/SM.
#define BSTR 40                        // bf16 elems per smem row (80 B, conflict-free)
#define PLANEB (128 * BSTR)            // bf16 elems per plane
#define STAGEB (4 * PLANEB * 2)        // bytes per stage (A hi/lo + W hi/lo)
#define GSMEM2 (2 * STAGEB)            // 81,920 B
#define GRPM 18

template<int ACT>
__global__ __launch_bounds__(256, 2)
void gemm_dual(const uint16_t* __restrict__ Ah, const uint16_t* __restrict__ Al,
               const uint16_t* __restrict__ Wfh, const uint16_t* __restrict__ Wfl,
               const uint16_t* __restrict__ Wbh, const uint16_t* __restrict__ Wbl,
               const float* __restrict__ biasf, const float* __restrict__ biasb,
               float* __restrict__ Cf, float* __restrict__ Cb,
               int M, int N, int K, int tilesPer)
{
    extern __shared__ uint16_t smem16[];

    const int tid  = threadIdx.x;
    const int wid  = tid >> 5;
    const int lane = tid & 31;
    const int wm   = wid & 1;
    const int wn   = wid >> 1;
    const int lq   = lane >> 2;
    const int lr   = lane & 3;

    int bid = blockIdx.x;
    const int half = (bid >= tilesPer) ? 1 : 0;
    bid -= half * tilesPer;
    const uint16_t* Wh   = half ? Wbh : Wfh;
    const uint16_t* Wl   = half ? Wbl : Wfl;
    const float*    bias = half ? biasb : biasf;
    float*          C    = half ? Cb : Cf;
    const bool      flip = (half != 0);

    // group swizzle: bid -> (mt, nt)
    const int NT = N >> 7;
    const int MT = M >> 7;
    int per_group = NT * GRPM;
    int grp  = bid / per_group;
    int rem  = bid - grp * per_group;
    int gm0  = grp * GRPM;
    int rows = MT - gm0; if (rows > GRPM) rows = GRPM;
    const int m0 = (gm0 + (rem % rows)) * 128;
    const int n0 = (rem / rows) * 128;

    const uint32_t sbase = smem_u32(smem16);

    float acc[4][4][4];
#pragma unroll
    for (int i = 0; i < 4; i++)
#pragma unroll
        for (int j = 0; j < 4; j++)
#pragma unroll
            for (int r = 0; r < 4; r++) acc[i][j][r] = 0.f;

    const int nk = K >> 5;   // K multiple of 32 guaranteed

    auto arow_of = [&](int r) {
        int gm = m0 + r;
        if (flip) { int bI = gm >> 8; int t = gm & 255; return (bI << 8) + (255 - t); }
        return gm;
    };

    const uint16_t* srcs[4] = {Ah, Al, Wh, Wl};

    // per chunk: 4 planes x 128 rows x 4 x 16B = 2048 copies -> 8 per thread
    auto load_chunk = [&](int kc, int buf) {
        const int k0 = kc * 32;
        const uint32_t boff = (uint32_t)buf * STAGEB;
#pragma unroll
        for (int i = 0; i < 8; i++) {
            int s = tid + i * 256;
            int p = s >> 9;                 // plane 0..3
            int r = (s >> 2) & 127;
            int c = s & 3;                  // 16B (8-elem) column
            uint32_t dst = sbase + boff + (uint32_t)p * (PLANEB * 2)
                         + (uint32_t)(r * BSTR * 2 + c * 16);
            int grow = (p < 2) ? arow_of(r) : (n0 + r);
            cp_async16(dst, srcs[p] + (size_t)grow * K + k0 + c * 8);
        }
        cp_commit();
    };

    load_chunk(0, 0);

    for (int kc = 0; kc < nk; kc++) {
        cp_wait0();
        __syncthreads();
        if (kc + 1 < nk) load_chunk(kc + 1, (kc + 1) & 1);

        const uint16_t* base = smem16 + (size_t)(kc & 1) * (STAGEB / 2);
        const uint16_t* bAh = base;
        const uint16_t* bAl = base + PLANEB;
        const uint16_t* bWh = base + 2 * PLANEB;
        const uint16_t* bWl = base + 3 * PLANEB;

#pragma unroll
        for (int ks = 0; ks < 2; ks++) {
            const int kk = ks * 16 + 2 * lr;
            // W fragments for all 4 n-tiles
            uint32_t bh[4][2], bl[4][2];
#pragma unroll
            for (int nt = 0; nt < 4; nt++) {
                int brow = wn * 32 + nt * 8 + lq;
                bh[nt][0] = *(const uint32_t*)(bWh + brow * BSTR + kk);
                bh[nt][1] = *(const uint32_t*)(bWh + brow * BSTR + kk + 8);
                bl[nt][0] = *(const uint32_t*)(bWl + brow * BSTR + kk);
                bl[nt][1] = *(const uint32_t*)(bWl + brow * BSTR + kk + 8);
            }
#pragma unroll
            for (int mt = 0; mt < 4; mt++) {
                int row0 = wm * 64 + mt * 16 + lq;
                uint32_t ahi[4], alo[4];
                ahi[0] = *(const uint32_t*)(bAh + row0 * BSTR + kk);
                ahi[1] = *(const uint32_t*)(bAh + (row0 + 8) * BSTR + kk);
                ahi[2] = *(const uint32_t*)(bAh + row0 * BSTR + kk + 8);
                ahi[3] = *(const uint32_t*)(bAh + (row0 + 8) * BSTR + kk + 8);
                alo[0] = *(const uint32_t*)(bAl + row0 * BSTR + kk);
                alo[1] = *(const uint32_t*)(bAl + (row0 + 8) * BSTR + kk);
                alo[2] = *(const uint32_t*)(bAl + row0 * BSTR + kk + 8);
                alo[3] = *(const uint32_t*)(bAl + (row0 + 8) * BSTR + kk + 8);
#pragma unroll
                for (int nt = 0; nt < 4; nt++) {
                    mma_bf16(acc[mt][nt], ahi, bh[nt]);
                    mma_bf16(acc[mt][nt], alo, bh[nt]);
                    mma_bf16(acc[mt][nt], ahi, bl[nt]);
                }
            }
        }
    }

    const int rbase = m0 + wm * 64;
    const int cbase = n0 + wn * 32;
#pragma unroll
    for (int mt = 0; mt < 4; mt++) {
#pragma unroll
        for (int nt = 0; nt < 4; nt++) {
            int c  = cbase + nt * 8 + lr * 2;
            float b0v = bias[c], b1v = bias[c + 1];
            int r0 = rbase + mt * 16 + lq;
            float v0 = acc[mt][nt][0] + b0v;
            float v1 = acc[mt][nt][1] + b1v;
            float v2 = acc[mt][nt][2] + b0v;
            float v3 = acc[mt][nt][3] + b1v;
            if (ACT == 1) { v0 = tanhf(v0); v1 = tanhf(v1); v2 = tanhf(v2); v3 = tanhf(v3); }
            *(float2*)(C + (size_t)r0 * N + c)       = make_float2(v0, v1);
            *(float2*)(C + (size_t)(r0 + 8) * N + c) = make_float2(v2, v3);
        }
    }
}

// ---------------- persistent LSTM: bf16 hi/lo split (m16n8k16), cp.async h ----------------
#define WPLANE (8 * 32 * 104)
#define HSTRL 72
#define SMEM_LSTM (2 * WPLANE * 2 + 2 * 128 * HSTRL * 4)

__global__ __launch_bounds__(256, 1)
void lstm_mma(const float* __restrict__ xpF, const float* __restrict__ xpB,
              const float* __restrict__ whF, const float* __restrict__ whB,
              float* __restrict__ hout_f32,
              uint16_t* __restrict__ hh, uint16_t* __restrict__ hl)
{
    extern __shared__ char smemc[];
    __nv_bfloat16* sWhi = (__nv_bfloat16*)smemc;
    __nv_bfloat16* sWlo = sWhi + WPLANE;
    float* sH = (float*)(smemc + 2 * WPLANE * 2);
    __shared__ unsigned s_gen;

    const int tid  = threadIdx.x;
    const int bi   = blockIdx.x;
    const int w    = tid >> 5;
    const int lane = tid & 31;
    const int lq   = lane >> 2;
    const int lr   = lane & 3;
    const int dir  = bi >> 6;
    const int j0   = (bi & 63) * 8;
    const int w16  = w * 16;
    const float* wh = dir ? whB : whF;
    const float* xp = dir ? xpB : xpF;
    const uint32_t sH_base = smem_u32(sH);

    for (int e = tid; e < 32 * 512; e += 256) {
        int n = e >> 9, k = e & 511;
        int c = k >> 6, kin = k & 63;
        int grow = (n >> 3) * 512 + j0 + (n & 7);
        float v = wh[(size_t)grow * HH + k];
        __nv_bfloat16 hb = __float2bfloat16_rn(v);
        float hf = __bfloat162float(hb);
        __nv_bfloat16 lb = __float2bfloat16_rn(v - hf);
        int idx = (c * 32 + n) * 104 + kin;
        sWhi[idx] = hb;
        sWlo[idx] = lb;
    }
    __syncthreads();

    float creg[4] = {0.f, 0.f, 0.f, 0.f};

    float2 xg2[2][4];
#pragma unroll
    for (int bb = 0; bb < 2; bb++) {
        const float* xr = xp + ((size_t)(w16 + lq + bb * 8) * TT + 0) * GG + j0 + lr * 2;
        xg2[bb][0] = *(const float2*)(xr);
        xg2[bb][1] = *(const float2*)(xr + 512);
        xg2[bb][2] = *(const float2*)(xr + 1024);
        xg2[bb][3] = *(const float2*)(xr + 1536);
    }

    for (int t = 0; t < TT; t++) {
        float acc[4][4];
#pragma unroll
        for (int nt = 0; nt < 4; nt++)
#pragma unroll
            for (int r = 0; r < 4; r++) acc[nt][r] = 0.f;

        if (t > 0) {
            const float* hprev = g_hping + ((((t - 1) & 1) << 1) + dir) * (BB * HH);

            auto load_hchunk = [&](int kc, int buf) {
                const uint32_t boff = (uint32_t)buf * 128 * HSTRL * 4;
#pragma unroll
                for (int i = 0; i < 8; i++) {
                    int s   = tid + i * 256;
                    int row = s >> 4;
                    int c4  = s & 15;
                    cp_async16(sH_base + boff + (uint32_t)(row * HSTRL + c4 * 4) * 4,
                               hprev + row * 512 + kc * 64 + c4 * 4);
                }
                cp_commit();
            };

            load_hchunk(0, 0);
            for (int kc = 0; kc < 8; kc++) {
                cp_wait0();
                __syncthreads();
                if (kc < 7) load_hchunk(kc + 1, (kc + 1) & 1);

                const float* bH = sH + (kc & 1) * 128 * HSTRL;
                const __nv_bfloat16* Wchi = sWhi + kc * 32 * 104;
                const __nv_bfloat16* Wclo = sWlo + kc * 32 * 104;
#pragma unroll
                for (int ks = 0; ks < 4; ks++) {
                    const int kk = ks * 16 + 2 * lr;
                    const float* hr0 = bH + (w16 + lq)     * HSTRL;
                    const float* hr1 = bH + (w16 + lq + 8) * HSTRL;
                    float2 p00 = *(const float2*)(hr0 + kk);
                    float2 p10 = *(const float2*)(hr1 + kk);
                    float2 p01 = *(const float2*)(hr0 + kk + 8);
                    float2 p11 = *(const float2*)(hr1 + kk + 8);
                    uint32_t ahi[4], alo[4];
                    split_bf16x2(p00, ahi[0], alo[0]);
                    split_bf16x2(p10, ahi[1], alo[1]);
                    split_bf16x2(p01, ahi[2], alo[2]);
                    split_bf16x2(p11, ahi[3], alo[3]);
#pragma unroll
                    for (int nt = 0; nt < 4; nt++) {
                        const __nv_bfloat16* wr_hi = Wchi + (nt * 8 + lq) * 104 + kk;
                        const __nv_bfloat16* wr_lo = Wclo + (nt * 8 + lq) * 104 + kk;
                        uint32_t bhi[2], blo[2];
                        bhi[0] = *(const uint32_t*)(wr_hi);
                        bhi[1] = *(const uint32_t*)(wr_hi + 8);
                        blo[0] = *(const uint32_t*)(wr_lo);
                        blo[1] = *(const uint32_t*)(wr_lo + 8);
                        mma_bf16(acc[nt], ahi, bhi);
                        mma_bf16(acc[nt], alo, bhi);
                        mma_bf16(acc[nt], ahi, blo);
                    }
                }
            }
        }

        const int tt = dir ? (TT - 1 - t) : t;
        float* hnext = g_hping + (((t & 1) << 1) + dir) * (BB * HH);
#pragma unroll
        for (int bb = 0; bb < 2; bb++) {
            int b = w16 + lq + bb * 8;
            int i0 = bb * 2;

            float zi = acc[0][i0] + xg2[bb][0].x, zf = acc[1][i0] + xg2[bb][1].x;
            float zg = acc[2][i0] + xg2[bb][2].x, zo = acc[3][i0] + xg2[bb][3].x;
            float si = 1.f / (1.f + __expf(-zi));
            float sf = 1.f / (1.f + __expf(-zf));
            float so = 1.f / (1.f + __expf(-zo));
            float tg = tanhf(zg);
            creg[i0] = sf * creg[i0] + si * tg;
            float h0v = so * tanhf(creg[i0]);

            zi = acc[0][i0 + 1] + xg2[bb][0].y; zf = acc[1][i0 + 1] + xg2[bb][1].y;
            zg = acc[2][i0 + 1] + xg2[bb][2].y; zo = acc[3][i0 + 1] + xg2[bb][3].y;
            si = 1.f / (1.f + __expf(-zi));
            sf = 1.f / (1.f + __expf(-zf));
            so = 1.f / (1.f + __expf(-zo));
            tg = tanhf(zg);
            creg[i0 + 1] = sf * creg[i0 + 1] + si * tg;
            float h1v = so * tanhf(creg[i0 + 1]);

            float2 hv = make_float2(h0v, h1v);
            *(float2*)(hnext + b * 512 + j0 + lr * 2) = hv;

            size_t oidx = ((size_t)b * TT + tt) * HD2 + dir * 512 + j0 + lr * 2;
            if (hout_f32) *(float2*)(hout_f32 + oidx) = hv;
            uint32_t hiu, lou;
            split_bf16x2(hv, hiu, lou);
            *(uint32_t*)(hh + oidx) = hiu;
            *(uint32_t*)(hl + oidx) = lou;
        }

        // barrier: arrive
        __syncthreads();
        if (tid == 0) {
            __threadfence();
            s_gen = atomicAdd(&g_bgen2[dir], 0u);
            if (atomicAdd(&g_bcnt2[dir], 1u) == 63u) {
                atomicExch(&g_bcnt2[dir], 0u);
                __threadfence();
                atomicAdd(&g_bgen2[dir], 1u);
            }
        }

        // prefetch xproj for t+1
        if (t + 1 < TT) {
#pragma unroll
            for (int bb = 0; bb < 2; bb++) {
                const float* xr = xp + ((size_t)(w16 + lq + bb * 8) * TT + (t + 1)) * GG + j0 + lr * 2;
                xg2[bb][0] = *(const float2*)(xr);
                xg2[bb][1] = *(const float2*)(xr + 512);
                xg2[bb][2] = *(const float2*)(xr + 1024);
                xg2[bb][3] = *(const float2*)(xr + 1536);
            }
        }

        // barrier: wait
        if (tid == 0) {
            unsigned gv = s_gen;
            while (atomicAdd(&g_bgen2[dir], 0u) == gv) { __nanosleep(20); }
        }
        __syncthreads();
    }
}

// ---------------- tail kernels ----------------
__global__ void scores_k(const float* __restrict__ th, const float* __restrict__ aw2,
                         const float* __restrict__ ab2, float* __restrict__ sc)
{
    int r = blockIdx.x;
    const float* row = th + (size_t)r * HD2;
    float s = 0.f;
    for (int k = threadIdx.x; k < HD2; k += 128) s += row[k] * aw2[k];
    __shared__ float red[128];
    red[threadIdx.x] = s; __syncthreads();
    for (int o = 64; o > 0; o >>= 1) {
        if (threadIdx.x < o) red[threadIdx.x] += red[threadIdx.x + o];
        __syncthreads();
    }
    if (threadIdx.x == 0) sc[r] = red[0] + ab2[0];
}

__global__ void softmax_k(const float* __restrict__ sc, float* __restrict__ attw,
                          float* __restrict__ out_attw)
{
    int b = blockIdx.x, t = threadIdx.x;
    float v = sc[b * TT + t];
    __shared__ float red[TT];
    red[t] = v; __syncthreads();
    for (int o = 128; o > 0; o >>= 1) {
        if (t < o) red[t] = fmaxf(red[t], red[t + o]);
        __syncthreads();
    }
    float mx = red[0]; __syncthreads();
    float e = __expf(v - mx);
    red[t] = e; __syncthreads();
    for (int o = 128; o > 0; o >>= 1) {
        if (t < o) red[t] += red[t + o];
        __syncthreads();
    }
    float w = e / red[0];
    attw[b * TT + t] = w;
    if (out_attw) out_attw[b * TT + t] = w;
}

__global__ void context_k(const float* __restrict__ attw, const float* __restrict__ lo,
                          float* __restrict__ ctx)
{
    int b = blockIdx.y;
    int n = blockIdx.x * 256 + threadIdx.x;
    __shared__ float aw[TT];
    aw[threadIdx.x] = attw[b * TT + threadIdx.x];
    __syncthreads();
    float s = 0.f;
    const float* base = lo + (size_t)b * TT * HD2 + n;
#pragma unroll 4
    for (int t = 0; t < TT; t++) s += aw[t] * base[(size_t)t * HD2];
    ctx[b * HD2 + n] = s;
}

__global__ void cls1_k(const float* __restrict__ ctx, const float* __restrict__ w,
                       const float* __restrict__ bias, float* __restrict__ hc)
{
    int b = blockIdx.x, j = threadIdx.x;
    __shared__ float xs[HD2];
    xs[j] = ctx[b * HD2 + j];
    xs[j + 512] = ctx[b * HD2 + j + 512];
    __syncthreads();
    float s = bias[j];
    for (int k = 0; k < HD2; k++) s += xs[k] * w[k * HH + j];
    hc[b * HH + j] = fmaxf(s, 0.f);
}

__global__ void cls2_k(const float* __restrict__ hc, const float* __restrict__ w,
                       const float* __restrict__ bias, float* __restrict__ out)
{
    int b = blockIdx.x, j = threadIdx.x;
    __shared__ float xs[HH];
    for (int k = j; k < HH; k += 128) xs[k] = hc[b * HH + k];
    __syncthreads();
    if (j < NC) {
        float s = bias[j];
        for (int k = 0; k < HH; k++) s += xs[k] * w[k * NC + j];
        out[b * NC + j] = s;
    }
}

// ---------------- launch ----------------
extern "C" void kernel_launch(void* const* d_in, const int* in_sizes, int n_in,
                              void* d_out, int out_size)
{
    const float* x     = (const float*)d_in[0];
    const float* wih0f = (const float*)d_in[1];
    const float* whh0f = (const float*)d_in[2];
    const float* b0f   = (const float*)d_in[3];
    const float* wih0b = (const float*)d_in[4];
    const float* whh0b = (const float*)d_in[5];
    const float* b0b   = (const float*)d_in[6];
    const float* wih1f = (const float*)d_in[7];
    const float* whh1f = (const float*)d_in[8];
    const float* b1f   = (const float*)d_in[9];
    const float* wih1b = (const float*)d_in[10];
    const float* whh1b = (const float*)d_in[11];
    const float* b1b   = (const float*)d_in[12];
    const float* aw1   = (const float*)d_in[13];
    const float* ab1   = (const float*)d_in[14];
    const float* aw2   = (const float*)d_in[15];
    const float* ab2   = (const float*)d_in[16];
    const float* cw1   = (const float*)d_in[17];
    const float* cb1   = (const float*)d_in[18];
    const float* cw2   = (const float*)d_in[19];
    const float* cb2   = (const float*)d_in[20];
    float* out = (float*)d_out;

    float *xpf, *xpb, *lo, *sc, *aw, *ctx, *hc;
    uint16_t *xh, *xl, *w0fh, *w0fl, *w0bh, *w0bl, *w1fh, *w1fl, *w1bh, *w1bl;
    uint16_t *h0h, *h0l, *loh, *lol, *awth, *awtl;
    cudaGetSymbolAddress((void**)&xpf, g_xpf);
    cudaGetSymbolAddress((void**)&xpb, g_xpb);
    cudaGetSymbolAddress((void**)&lo,  g_outbuf);
    cudaGetSymbolAddress((void**)&sc,  g_scoresb);
    cudaGetSymbolAddress((void**)&aw,  g_attwb);
    cudaGetSymbolAddress((void**)&ctx, g_ctx);
    cudaGetSymbolAddress((void**)&hc,  g_hc);
    cudaGetSymbolAddress((void**)&xh,   g_xh);
    cudaGetSymbolAddress((void**)&xl,   g_xl);
    cudaGetSymbolAddress((void**)&w0fh, g_w0fh);
    cudaGetSymbolAddress((void**)&w0fl, g_w0fl);
    cudaGetSymbolAddress((void**)&w0bh, g_w0bh);
    cudaGetSymbolAddress((void**)&w0bl, g_w0bl);
    cudaGetSymbolAddress((void**)&w1fh, g_w1fh);
    cudaGetSymbolAddress((void**)&w1fl, g_w1fl);
    cudaGetSymbolAddress((void**)&w1bh, g_w1bh);
    cudaGetSymbolAddress((void**)&w1bl, g_w1bl);
    cudaGetSymbolAddress((void**)&h0h,  g_h0h);
    cudaGetSymbolAddress((void**)&h0l,  g_h0l);
    cudaGetSymbolAddress((void**)&loh,  g_loh);
    cudaGetSymbolAddress((void**)&lol,  g_lol);
    cudaGetSymbolAddress((void**)&awth, g_awth);
    cudaGetSymbolAddress((void**)&awtl, g_awtl);

    cudaFuncSetAttribute(gemm_dual<0>, cudaFuncAttributeMaxDynamicSharedMemorySize, GSMEM2);
    cudaFuncSetAttribute(gemm_dual<1>, cudaFuncAttributeMaxDynamicSharedMemorySize, GSMEM2);
    cudaFuncSetAttribute(lstm_mma, cudaFuncAttributeMaxDynamicSharedMemorySize, SMEM_LSTM);

    // split passes
    split_pad_k<<<2048, 256>>>(x,     xh,   xl,   BT, INN, KP0);
    split_pad_k<<<512, 256>>>(wih0f, w0fh, w0fl, GG, INN, KP0);
    split_pad_k<<<512, 256>>>(wih0b, w0bh, w0bl, GG, INN, KP0);
    split_pad_k<<<512, 256>>>(wih1f, w1fh, w1fl, GG, HD2, HD2);
    split_pad_k<<<512, 256>>>(wih1b, w1bh, w1bl, GG, HD2, HD2);
    transpose_split_k<<<dim3(HD2 / 32, HD2 / 32), dim3(32, 32)>>>(aw1, awth, awtl, HD2, HD2);

    dim3 blk(256);
    const int TILES_P = (GG / 128) * (BT / 128);    // 4096
    const int TILES_A = (HD2 / 128) * (BT / 128);   // 2048

    // layer 0: fwd + bwd fused
    gemm_dual<0><<<2 * TILES_P, blk, GSMEM2>>>(xh, xl, w0fh, w0fl, w0bh, w0bl,
                                               b0f, b0b, xpf, xpb, BT, GG, KP0, TILES_P);
    lstm_mma<<<128, 256, SMEM_LSTM>>>(xpf, xpb, whh0f, whh0b, nullptr, h0h, h0l);

    // layer 1: fwd + bwd fused
    gemm_dual<0><<<2 * TILES_P, blk, GSMEM2>>>(h0h, h0l, w1fh, w1fl, w1bh, w1bl,
                                               b1f, b1b, xpf, xpb, BT, GG, HD2, TILES_P);
    lstm_mma<<<128, 256, SMEM_LSTM>>>(xpf, xpb, whh1f, whh1b, lo, loh, lol);

    // attention GEMM
    gemm_dual<1><<<TILES_A, blk, GSMEM2>>>(loh, lol, awth, awtl, awth, awtl,
                                           ab1, ab1, xpf, xpf, BT, HD2, HD2, TILES_A);
    scores_k<<<BT, 128>>>(xpf, aw2, ab2, sc);

    float* out_attw = (out_size >= (BB * NC + BT)) ? (out + BB * NC) : nullptr;
    softmax_k<<<BB, TT>>>(sc, aw, out_attw);
    context_k<<<dim3(HD2 / 256, BB), 256>>>(aw, lo, ctx);
    cls1_k<<<BB, 512>>>(ctx, cw1, cb1, hc);
    cls2_k<<<BB, 128>>>(hc, cw2, cb2, out);
}